// round 8
// baseline (speedup 1.0000x reference)
#include <cuda_runtime.h>

#define NB 32
#define NL 100
#define NT (NB*NL)      // 3200 tokens
#define ND 200
#define INDIM 360
#define EMBD 300
#define POSD 30
#define NERD 30
#define NREL 40

#define BM 32           // tokens per block tile (GEMM)
#define BN 64           // outputs per block tile (GEMM)
#define KC 16           // k chunk
#define AGG_ROWS 4      // l rows per agg block
#define MH 50           // m per half (two warp-groups split the m range)

typedef unsigned long long ull;

__device__ float g_xa[NT*INDIM];
__device__ float g_xb[NT*ND];
__device__ float g_z[NT*ND];
__device__ float g_invden[NT];

__device__ __forceinline__ void fma2(ull& acc, ull a, ull b) {
    asm("fma.rn.f32x2 %0, %1, %2, %0;" : "+l"(acc) : "l"(a), "l"(b));
}
__device__ __forceinline__ ull add2(ull a, ull b) {
    ull r;
    asm("add.rn.f32x2 %0, %1, %2;" : "=l"(r) : "l"(a), "l"(b));
    return r;
}

// ---------------------------------------------------------------------------
// denom + mask
// ---------------------------------------------------------------------------
__global__ void denom_mask_kernel(const int* __restrict__ adj,
                                  float* __restrict__ out_mask,
                                  int write_mask) {
    __shared__ int A[NL*NL];     // 40 KB
    int b = blockIdx.x;
    int tid = threadIdx.x;
    const int* src = adj + b*NL*NL;
    for (int i = tid; i < NL*NL; i += blockDim.x) A[i] = src[i];
    __syncthreads();
    if (tid < NL) {
        int rc = 0, cc = 0;
        #pragma unroll 4
        for (int m = 0; m < NL; m++) {
            rc += (A[tid*NL + m] != 0);
            cc += (A[m*NL + tid] != 0);
        }
        g_invden[b*NL + tid] = 1.0f / (float)(rc + 1);
        if (write_mask)
            out_mask[b*NL + tid] = (rc + cc == 0) ? 1.0f : 0.0f;
    }
}

// ---------------------------------------------------------------------------
// Embedding gather: one block per token
// ---------------------------------------------------------------------------
__global__ void gather_kernel(const int* __restrict__ words,
                              const int* __restrict__ pos,
                              const int* __restrict__ ner,
                              const float* __restrict__ emb,
                              const float* __restrict__ pos_emb,
                              const float* __restrict__ ner_emb,
                              float* __restrict__ xout) {
    int tok = blockIdx.x;
    int k = threadIdx.x;
    if (k >= INDIM) return;
    float v;
    if (k < EMBD)            v = emb[words[tok]*EMBD + k];
    else if (k < EMBD+POSD)  v = pos_emb[pos[tok]*POSD + (k - EMBD)];
    else                     v = ner_emb[ner[tok]*NERD + (k - EMBD - POSD)];
    xout[tok*INDIM + k] = v;
}

// ---------------------------------------------------------------------------
// Double-buffered register-tiled SGEMM: C[M x 200] = A[M x K] . B[200 x K]^T
// Block 32x64, 256 thr, 2x4 per thread (R6 config — measured winner).
// MODE 0: C = acc + bias[j]
// MODE 1: C = relu((acc + 2*bias[j]) * invden[t])
// ---------------------------------------------------------------------------
template<int K, int MODE>
__global__ __launch_bounds__(256) void gemm_kernel(const float* __restrict__ A,
                                                   const float* __restrict__ B,
                                                   const float* __restrict__ bias,
                                                   float* __restrict__ C) {
    const int NC = (K + KC - 1) / KC;
    __shared__ __align__(16) float As[2][KC][BM+4];
    __shared__ __align__(16) float Bs[2][KC][BN+4];
    int tid = threadIdx.x;
    int tx = tid & 15, ty = tid >> 4;
    int t0 = blockIdx.x * BM;
    int j0 = blockIdx.y * BN;

    int lkk = tid & 15;
    int lrow = tid >> 4;         // 0..15

    float rA[2], rB[4];

    // --- preload chunk 0 ---
    {
        #pragma unroll
        for (int it = 0; it < 2; it++) {
            int t = lrow + it*16;
            rA[it] = (lkk < K) ? A[(t0 + t)*K + lkk] : 0.f;
        }
        #pragma unroll
        for (int it = 0; it < 4; it++) {
            int j = lrow + it*16;
            rB[it] = (lkk < K && (j0 + j) < ND) ? B[(j0 + j)*K + lkk] : 0.f;
        }
        #pragma unroll
        for (int it = 0; it < 2; it++) As[0][lkk][lrow + it*16] = rA[it];
        #pragma unroll
        for (int it = 0; it < 4; it++) Bs[0][lkk][lrow + it*16] = rB[it];
    }
    __syncthreads();

    float acc[2][4];
    #pragma unroll
    for (int i = 0; i < 2; i++)
        #pragma unroll
        for (int j = 0; j < 4; j++) acc[i][j] = 0.f;

    for (int c = 0; c < NC; c++) {
        int cur = c & 1;
        if (c + 1 < NC) {
            int k = (c + 1) * KC + lkk;
            #pragma unroll
            for (int it = 0; it < 2; it++) {
                int t = lrow + it*16;
                rA[it] = (k < K) ? A[(t0 + t)*K + k] : 0.f;
            }
            #pragma unroll
            for (int it = 0; it < 4; it++) {
                int j = lrow + it*16;
                rB[it] = (k < K && (j0 + j) < ND) ? B[(j0 + j)*K + k] : 0.f;
            }
        }
        #pragma unroll
        for (int kk = 0; kk < KC; kk++) {
            float2 a = *(const float2*)&As[cur][kk][2*tx];
            float4 b = *(const float4*)&Bs[cur][kk][4*ty];
            acc[0][0] += a.x*b.x; acc[0][1] += a.x*b.y; acc[0][2] += a.x*b.z; acc[0][3] += a.x*b.w;
            acc[1][0] += a.y*b.x; acc[1][1] += a.y*b.y; acc[1][2] += a.y*b.z; acc[1][3] += a.y*b.w;
        }
        if (c + 1 < NC) {
            int nxt = cur ^ 1;
            #pragma unroll
            for (int it = 0; it < 2; it++) As[nxt][lkk][lrow + it*16] = rA[it];
            #pragma unroll
            for (int it = 0; it < 4; it++) Bs[nxt][lkk][lrow + it*16] = rB[it];
        }
        __syncthreads();
    }

    int tbase = t0 + 2*tx;
    int jbase = j0 + 4*ty;
    #pragma unroll
    for (int i = 0; i < 2; i++) {
        int tok = tbase + i;
        float inv = (MODE == 1) ? g_invden[tok] : 0.f;
        float4 v;
        if (MODE == 0) {
            v.x = acc[i][0] + bias[jbase];
            v.y = acc[i][1] + bias[jbase+1];
            v.z = acc[i][2] + bias[jbase+2];
            v.w = acc[i][3] + bias[jbase+3];
        } else {
            v.x = fmaxf((acc[i][0] + 2.f*bias[jbase])   * inv, 0.f);
            v.y = fmaxf((acc[i][1] + 2.f*bias[jbase+1]) * inv, 0.f);
            v.z = fmaxf((acc[i][2] + 2.f*bias[jbase+2]) * inv, 0.f);
            v.w = fmaxf((acc[i][3] + 2.f*bias[jbase+3]) * inv, 0.f);
        }
        if (jbase + 3 < ND)
            *(float4*)&C[tok*ND + jbase] = v;
        else {
            if (jbase   < ND) C[tok*ND + jbase]   = v.x;
            if (jbase+1 < ND) C[tok*ND + jbase+1] = v.y;
            if (jbase+2 < ND) C[tok*ND + jbase+2] = v.z;
            if (jbase+3 < ND) C[tok*ND + jbase+3] = v.w;
        }
    }
}

// ---------------------------------------------------------------------------
// Aggregation: Z[b,l,d] = x[b,l,d] + sum_m E[adj[b,l,m], d] * x[b,m,d]
// 4 rows/block, 256 threads, two warp-groups split the m range. Each thread
// owns a d-pair (f32x2). x loads double-buffered, prefetch distance 10 m's
// (2 chunks of 5) to cover L2 latency. Halves combined via smem partials.
// ---------------------------------------------------------------------------
__global__ __launch_bounds__(256) void agg_kernel(const int* __restrict__ adj,
                                                  const float* __restrict__ dep,
                                                  const float* __restrict__ x,
                                                  float* __restrict__ z) {
    __shared__ __align__(16) float Es[NREL*ND];        // 32 KB
    __shared__ __align__(16) int adjs[NL*4];           // 1.6 KB
    __shared__ __align__(16) float part[AGG_ROWS][ND]; // 3.2 KB
    int tid = threadIdx.x;
    int b = blockIdx.y;
    int l0 = blockIdx.x * AGG_ROWS;

    int dp = tid & 127;
    int mh = tid >> 7;
    bool active = dp < ND/2;

    // init accumulators early (mh0 row loads overlap Es staging)
    ull acc[AGG_ROWS];
    if (active && mh == 0) {
        #pragma unroll
        for (int i = 0; i < AGG_ROWS; i++)
            acc[i] = *(const ull*)&x[(b*NL + l0 + i)*ND + 2*dp];
    } else {
        #pragma unroll
        for (int i = 0; i < AGG_ROWS; i++) acc[i] = 0ull;
    }

    // stage Es (float4) and adjs
    {
        const float4* d4 = (const float4*)dep;
        float4* e4 = (float4*)Es;
        for (int i = tid; i < NREL*ND/4; i += 256) e4[i] = d4[i];
        for (int i = tid; i < AGG_ROWS*NL; i += 256) {
            int j = i & 3, m = i >> 2;
            adjs[i] = adj[(b*NL + l0 + j)*NL + m] * (ND*4);
        }
    }
    __syncthreads();

    if (active) {
        const char* ep = (const char*)Es + 8*dp;
        const float* xb = x + b*NL*ND + 2*dp + mh*MH*ND;
        const int*  ap = adjs + mh*MH*4;

        // double-buffered prefetch: 2 chunks of 5 in flight
        ull xv[2][5];
        #pragma unroll
        for (int s = 0; s < 5; s++) {
            xv[0][s] = *(const ull*)(xb + s*ND);
            xv[1][s] = *(const ull*)(xb + (5 + s)*ND);
        }

        #pragma unroll 1
        for (int ch = 0; ch < MH/5; ch++) {
            int buf = ch & 1;
            ull cv[5];
            #pragma unroll
            for (int s = 0; s < 5; s++) cv[s] = xv[buf][s];
            if (ch + 2 < MH/5) {
                const float* px = xb + (ch + 2)*5*ND;
                #pragma unroll
                for (int s = 0; s < 5; s++)
                    xv[buf][s] = *(const ull*)(px + s*ND);
            }
            const int* apc = ap + ch*5*4;
            #pragma unroll
            for (int s = 0; s < 5; s++) {
                const int4 r03 = *(const int4*)&apc[s*4];
                fma2(acc[0], *(const ull*)(ep + r03.x), cv[s]);
                fma2(acc[1], *(const ull*)(ep + r03.y), cv[s]);
                fma2(acc[2], *(const ull*)(ep + r03.z), cv[s]);
                fma2(acc[3], *(const ull*)(ep + r03.w), cv[s]);
            }
        }

        if (mh == 1) {
            #pragma unroll
            for (int i = 0; i < AGG_ROWS; i++)
                *(ull*)&part[i][2*dp] = acc[i];
        }
    }
    __syncthreads();
    if (active && mh == 0) {
        #pragma unroll
        for (int i = 0; i < AGG_ROWS; i++) {
            ull p = *(const ull*)&part[i][2*dp];
            *(ull*)&z[(b*NL + l0 + i)*ND + 2*dp] = add2(acc[i], p);
        }
    }
}

// ---------------------------------------------------------------------------
extern "C" void kernel_launch(void* const* d_in, const int* in_sizes, int n_in,
                              void* d_out, int out_size) {
    const int*   adj     = (const int*)  d_in[0];
    const int*   words   = (const int*)  d_in[1];
    const int*   pos     = (const int*)  d_in[2];
    const int*   ner     = (const int*)  d_in[3];
    const float* emb     = (const float*)d_in[4];
    const float* pos_emb = (const float*)d_in[5];
    const float* ner_emb = (const float*)d_in[6];
    const float* dep     = (const float*)d_in[7];
    const float* Wp      = (const float*)d_in[8];
    const float* bp      = (const float*)d_in[9];
    const float* W0      = (const float*)d_in[10];
    const float* b0      = (const float*)d_in[11];
    const float* W1      = (const float*)d_in[12];
    const float* b1      = (const float*)d_in[13];
    float* out = (float*)d_out;

    float *xa, *xb, *z;
    cudaGetSymbolAddress((void**)&xa, g_xa);
    cudaGetSymbolAddress((void**)&xb, g_xb);
    cudaGetSymbolAddress((void**)&z,  g_z);

    int write_mask = (out_size >= NT*ND + NT) ? 1 : 0;

    dim3 ggrid(NT/BM, (ND + BN - 1)/BN);        // (100, 4) = 400 blocks
    dim3 agrid(NL/AGG_ROWS, NB);                // (25, 32) = 800 blocks

    denom_mask_kernel<<<NB, 256>>>(adj, out + NT*ND, write_mask);
    gather_kernel<<<NT, 384>>>(words, pos, ner, emb, pos_emb, ner_emb, xa);
    gemm_kernel<INDIM, 0><<<ggrid, 256>>>(xa, Wp, bp, xb);
    agg_kernel<<<agrid, 256>>>(adj, dep, xb, z);
    gemm_kernel<ND, 1><<<ggrid, 256>>>(z, W0, b0, xb);
    agg_kernel<<<agrid, 256>>>(adj, dep, xb, z);
    gemm_kernel<ND, 1><<<ggrid, 256>>>(z, W1, b1, out);
}

// round 9
// speedup vs baseline: 1.1623x; 1.1623x over previous
#include <cuda_runtime.h>

#define NB 32
#define NL 100
#define NT (NB*NL)      // 3200 tokens
#define ND 200
#define INDIM 360
#define EMBD 300
#define POSD 30
#define NERD 30
#define NREL 40

#define BM 32           // tokens per block tile (GEMM)
#define BN 64           // outputs per block tile (GEMM)
#define KC 16           // k chunk
#define AGG_ROWS 4      // l rows per agg block
#define MH 50           // m per half (two warp-groups split the m range)

typedef unsigned long long ull;

__device__ float g_xa[NT*INDIM];
__device__ float g_xb[NT*ND];
__device__ float g_z[NT*ND];
__device__ float g_invden[NT];

__device__ __forceinline__ void fma2(ull& acc, ull a, ull b) {
    asm("fma.rn.f32x2 %0, %1, %2, %0;" : "+l"(acc) : "l"(a), "l"(b));
}
__device__ __forceinline__ ull add2(ull a, ull b) {
    ull r;
    asm("add.rn.f32x2 %0, %1, %2;" : "=l"(r) : "l"(a), "l"(b));
    return r;
}

// ---------------------------------------------------------------------------
// denom + mask
// ---------------------------------------------------------------------------
__global__ void denom_mask_kernel(const int* __restrict__ adj,
                                  float* __restrict__ out_mask,
                                  int write_mask) {
    __shared__ int A[NL*NL];     // 40 KB
    int b = blockIdx.x;
    int tid = threadIdx.x;
    const int* src = adj + b*NL*NL;
    for (int i = tid; i < NL*NL; i += blockDim.x) A[i] = src[i];
    __syncthreads();
    if (tid < NL) {
        int rc = 0, cc = 0;
        #pragma unroll 4
        for (int m = 0; m < NL; m++) {
            rc += (A[tid*NL + m] != 0);
            cc += (A[m*NL + tid] != 0);
        }
        g_invden[b*NL + tid] = 1.0f / (float)(rc + 1);
        if (write_mask)
            out_mask[b*NL + tid] = (rc + cc == 0) ? 1.0f : 0.0f;
    }
}

// ---------------------------------------------------------------------------
// Embedding gather: one block per token
// ---------------------------------------------------------------------------
__global__ void gather_kernel(const int* __restrict__ words,
                              const int* __restrict__ pos,
                              const int* __restrict__ ner,
                              const float* __restrict__ emb,
                              const float* __restrict__ pos_emb,
                              const float* __restrict__ ner_emb,
                              float* __restrict__ xout) {
    int tok = blockIdx.x;
    int k = threadIdx.x;
    if (k >= INDIM) return;
    float v;
    if (k < EMBD)            v = emb[words[tok]*EMBD + k];
    else if (k < EMBD+POSD)  v = pos_emb[pos[tok]*POSD + (k - EMBD)];
    else                     v = ner_emb[ner[tok]*NERD + (k - EMBD - POSD)];
    xout[tok*INDIM + k] = v;
}

// ---------------------------------------------------------------------------
// Double-buffered register-tiled SGEMM: C[M x 200] = A[M x K] . B[200 x K]^T
// Block 32x64, 256 thr, 2x4 per thread (R6 config — measured winner).
// MODE 0: C = acc + bias[j]
// MODE 1: C = relu((acc + 2*bias[j]) * invden[t])
// ---------------------------------------------------------------------------
template<int K, int MODE>
__global__ __launch_bounds__(256) void gemm_kernel(const float* __restrict__ A,
                                                   const float* __restrict__ B,
                                                   const float* __restrict__ bias,
                                                   float* __restrict__ C) {
    const int NC = (K + KC - 1) / KC;
    __shared__ __align__(16) float As[2][KC][BM+4];
    __shared__ __align__(16) float Bs[2][KC][BN+4];
    int tid = threadIdx.x;
    int tx = tid & 15, ty = tid >> 4;
    int t0 = blockIdx.x * BM;
    int j0 = blockIdx.y * BN;

    int lkk = tid & 15;
    int lrow = tid >> 4;         // 0..15

    float rA[2], rB[4];

    // --- preload chunk 0 ---
    {
        #pragma unroll
        for (int it = 0; it < 2; it++) {
            int t = lrow + it*16;
            rA[it] = (lkk < K) ? A[(t0 + t)*K + lkk] : 0.f;
        }
        #pragma unroll
        for (int it = 0; it < 4; it++) {
            int j = lrow + it*16;
            rB[it] = (lkk < K && (j0 + j) < ND) ? B[(j0 + j)*K + lkk] : 0.f;
        }
        #pragma unroll
        for (int it = 0; it < 2; it++) As[0][lkk][lrow + it*16] = rA[it];
        #pragma unroll
        for (int it = 0; it < 4; it++) Bs[0][lkk][lrow + it*16] = rB[it];
    }
    __syncthreads();

    float acc[2][4];
    #pragma unroll
    for (int i = 0; i < 2; i++)
        #pragma unroll
        for (int j = 0; j < 4; j++) acc[i][j] = 0.f;

    for (int c = 0; c < NC; c++) {
        int cur = c & 1;
        if (c + 1 < NC) {
            int k = (c + 1) * KC + lkk;
            #pragma unroll
            for (int it = 0; it < 2; it++) {
                int t = lrow + it*16;
                rA[it] = (k < K) ? A[(t0 + t)*K + k] : 0.f;
            }
            #pragma unroll
            for (int it = 0; it < 4; it++) {
                int j = lrow + it*16;
                rB[it] = (k < K && (j0 + j) < ND) ? B[(j0 + j)*K + k] : 0.f;
            }
        }
        #pragma unroll
        for (int kk = 0; kk < KC; kk++) {
            float2 a = *(const float2*)&As[cur][kk][2*tx];
            float4 b = *(const float4*)&Bs[cur][kk][4*ty];
            acc[0][0] += a.x*b.x; acc[0][1] += a.x*b.y; acc[0][2] += a.x*b.z; acc[0][3] += a.x*b.w;
            acc[1][0] += a.y*b.x; acc[1][1] += a.y*b.y; acc[1][2] += a.y*b.z; acc[1][3] += a.y*b.w;
        }
        if (c + 1 < NC) {
            int nxt = cur ^ 1;
            #pragma unroll
            for (int it = 0; it < 2; it++) As[nxt][lkk][lrow + it*16] = rA[it];
            #pragma unroll
            for (int it = 0; it < 4; it++) Bs[nxt][lkk][lrow + it*16] = rB[it];
        }
        __syncthreads();
    }

    int tbase = t0 + 2*tx;
    int jbase = j0 + 4*ty;
    #pragma unroll
    for (int i = 0; i < 2; i++) {
        int tok = tbase + i;
        float inv = (MODE == 1) ? g_invden[tok] : 0.f;
        float4 v;
        if (MODE == 0) {
            v.x = acc[i][0] + bias[jbase];
            v.y = acc[i][1] + bias[jbase+1];
            v.z = acc[i][2] + bias[jbase+2];
            v.w = acc[i][3] + bias[jbase+3];
        } else {
            v.x = fmaxf((acc[i][0] + 2.f*bias[jbase])   * inv, 0.f);
            v.y = fmaxf((acc[i][1] + 2.f*bias[jbase+1]) * inv, 0.f);
            v.z = fmaxf((acc[i][2] + 2.f*bias[jbase+2]) * inv, 0.f);
            v.w = fmaxf((acc[i][3] + 2.f*bias[jbase+3]) * inv, 0.f);
        }
        if (jbase + 3 < ND)
            *(float4*)&C[tok*ND + jbase] = v;
        else {
            if (jbase   < ND) C[tok*ND + jbase]   = v.x;
            if (jbase+1 < ND) C[tok*ND + jbase+1] = v.y;
            if (jbase+2 < ND) C[tok*ND + jbase+2] = v.z;
            if (jbase+3 < ND) C[tok*ND + jbase+3] = v.w;
        }
    }
}

// ---------------------------------------------------------------------------
// Aggregation: Z[b,l,d] = x[b,l,d] + sum_m E[adj[b,l,m], d] * x[b,m,d]
// 4 rows/block, 256 threads, two warp-groups split the m range. Each thread
// owns a d-pair (f32x2). x loads double-buffered in TWO STATIC register
// buffers (xv0/xv1, chunk loop unrolled x2 so all indices are compile-time —
// no dynamic-index local-memory spill). Halves combined via smem partials.
// ---------------------------------------------------------------------------
__global__ __launch_bounds__(256) void agg_kernel(const int* __restrict__ adj,
                                                  const float* __restrict__ dep,
                                                  const float* __restrict__ x,
                                                  float* __restrict__ z) {
    __shared__ __align__(16) float Es[NREL*ND];        // 32 KB
    __shared__ __align__(16) int adjs[NL*4];           // 1.6 KB
    __shared__ __align__(16) float part[AGG_ROWS][ND]; // 3.2 KB
    int tid = threadIdx.x;
    int b = blockIdx.y;
    int l0 = blockIdx.x * AGG_ROWS;

    int dp = tid & 127;
    int mh = tid >> 7;
    bool active = dp < ND/2;

    // init accumulators early (mh0 row loads overlap Es staging)
    ull acc[AGG_ROWS];
    if (active && mh == 0) {
        #pragma unroll
        for (int i = 0; i < AGG_ROWS; i++)
            acc[i] = *(const ull*)&x[(b*NL + l0 + i)*ND + 2*dp];
    } else {
        #pragma unroll
        for (int i = 0; i < AGG_ROWS; i++) acc[i] = 0ull;
    }

    // stage Es (float4) and adjs
    {
        const float4* d4 = (const float4*)dep;
        float4* e4 = (float4*)Es;
        for (int i = tid; i < NREL*ND/4; i += 256) e4[i] = d4[i];
        for (int i = tid; i < AGG_ROWS*NL; i += 256) {
            int j = i & 3, m = i >> 2;
            adjs[i] = adj[(b*NL + l0 + j)*NL + m] * (ND*4);
        }
    }
    __syncthreads();

    if (active) {
        const char* ep = (const char*)Es + 8*dp;
        const float* xb = x + b*NL*ND + 2*dp + mh*MH*ND;
        const int*  ap = adjs + mh*MH*4;

        // static double buffers: chunks of 5, loop unrolled x2
        ull xv0[5], xv1[5];
        #pragma unroll
        for (int s = 0; s < 5; s++) {
            xv0[s] = *(const ull*)(xb + s*ND);
            xv1[s] = *(const ull*)(xb + (5 + s)*ND);
        }

        #pragma unroll 1
        for (int ch = 0; ch < 10; ch += 2) {
            // --- even chunk (data in xv0) ---
            {
                ull cv[5];
                #pragma unroll
                for (int s = 0; s < 5; s++) cv[s] = xv0[s];
                if (ch + 2 < 10) {
                    const float* px = xb + (ch + 2)*5*ND;
                    #pragma unroll
                    for (int s = 0; s < 5; s++)
                        xv0[s] = *(const ull*)(px + s*ND);
                }
                const int* apc = ap + ch*5*4;
                #pragma unroll
                for (int s = 0; s < 5; s++) {
                    const int4 r03 = *(const int4*)&apc[s*4];
                    fma2(acc[0], *(const ull*)(ep + r03.x), cv[s]);
                    fma2(acc[1], *(const ull*)(ep + r03.y), cv[s]);
                    fma2(acc[2], *(const ull*)(ep + r03.z), cv[s]);
                    fma2(acc[3], *(const ull*)(ep + r03.w), cv[s]);
                }
            }
            // --- odd chunk (data in xv1) ---
            {
                ull cv[5];
                #pragma unroll
                for (int s = 0; s < 5; s++) cv[s] = xv1[s];
                if (ch + 3 < 10) {
                    const float* px = xb + (ch + 3)*5*ND;
                    #pragma unroll
                    for (int s = 0; s < 5; s++)
                        xv1[s] = *(const ull*)(px + s*ND);
                }
                const int* apc = ap + (ch + 1)*5*4;
                #pragma unroll
                for (int s = 0; s < 5; s++) {
                    const int4 r03 = *(const int4*)&apc[s*4];
                    fma2(acc[0], *(const ull*)(ep + r03.x), cv[s]);
                    fma2(acc[1], *(const ull*)(ep + r03.y), cv[s]);
                    fma2(acc[2], *(const ull*)(ep + r03.z), cv[s]);
                    fma2(acc[3], *(const ull*)(ep + r03.w), cv[s]);
                }
            }
        }

        if (mh == 1) {
            #pragma unroll
            for (int i = 0; i < AGG_ROWS; i++)
                *(ull*)&part[i][2*dp] = acc[i];
        }
    }
    __syncthreads();
    if (active && mh == 0) {
        #pragma unroll
        for (int i = 0; i < AGG_ROWS; i++) {
            ull p = *(const ull*)&part[i][2*dp];
            *(ull*)&z[(b*NL + l0 + i)*ND + 2*dp] = add2(acc[i], p);
        }
    }
}

// ---------------------------------------------------------------------------
extern "C" void kernel_launch(void* const* d_in, const int* in_sizes, int n_in,
                              void* d_out, int out_size) {
    const int*   adj     = (const int*)  d_in[0];
    const int*   words   = (const int*)  d_in[1];
    const int*   pos     = (const int*)  d_in[2];
    const int*   ner     = (const int*)  d_in[3];
    const float* emb     = (const float*)d_in[4];
    const float* pos_emb = (const float*)d_in[5];
    const float* ner_emb = (const float*)d_in[6];
    const float* dep     = (const float*)d_in[7];
    const float* Wp      = (const float*)d_in[8];
    const float* bp      = (const float*)d_in[9];
    const float* W0      = (const float*)d_in[10];
    const float* b0      = (const float*)d_in[11];
    const float* W1      = (const float*)d_in[12];
    const float* b1      = (const float*)d_in[13];
    float* out = (float*)d_out;

    float *xa, *xb, *z;
    cudaGetSymbolAddress((void**)&xa, g_xa);
    cudaGetSymbolAddress((void**)&xb, g_xb);
    cudaGetSymbolAddress((void**)&z,  g_z);

    int write_mask = (out_size >= NT*ND + NT) ? 1 : 0;

    dim3 ggrid(NT/BM, (ND + BN - 1)/BN);        // (100, 4) = 400 blocks
    dim3 agrid(NL/AGG_ROWS, NB);                // (25, 32) = 800 blocks

    denom_mask_kernel<<<NB, 256>>>(adj, out + NT*ND, write_mask);
    gather_kernel<<<NT, 384>>>(words, pos, ner, emb, pos_emb, ner_emb, xa);
    gemm_kernel<INDIM, 0><<<ggrid, 256>>>(xa, Wp, bp, xb);
    agg_kernel<<<agrid, 256>>>(adj, dep, xb, z);
    gemm_kernel<ND, 1><<<ggrid, 256>>>(z, W0, b0, xb);
    agg_kernel<<<agrid, 256>>>(adj, dep, xb, z);
    gemm_kernel<ND, 1><<<ggrid, 256>>>(z, W1, b1, out);
}

// round 10
// speedup vs baseline: 1.2504x; 1.0758x over previous
#include <cuda_runtime.h>

#define NB 32
#define NL 100
#define NT (NB*NL)      // 3200 tokens
#define ND 200
#define INDIM 360
#define EMBD 300
#define POSD 30
#define NERD 30
#define NREL 40

#define BM 32           // tokens per block tile (GEMM)
#define BN 64           // outputs per block tile (GEMM)
#define KC 16           // k chunk
#define AGG_ROWS 4      // l rows per agg block
#define MH 50           // m per half (two warp-groups split the m range)

typedef unsigned long long ull;

__device__ float g_xb[NT*ND];
__device__ float g_z[NT*ND];
__device__ float g_invden[NT];

__device__ __forceinline__ void fma2(ull& acc, ull a, ull b) {
    asm("fma.rn.f32x2 %0, %1, %2, %0;" : "+l"(acc) : "l"(a), "l"(b));
}
__device__ __forceinline__ ull add2(ull a, ull b) {
    ull r;
    asm("add.rn.f32x2 %0, %1, %2;" : "=l"(r) : "l"(a), "l"(b));
    return r;
}

// gather one element of the concatenated embedding row
__device__ __forceinline__ float gatherA(int k, int wofs, int pofs, int nofs,
                                         const float* __restrict__ emb,
                                         const float* __restrict__ pos_emb,
                                         const float* __restrict__ ner_emb) {
    if (k < EMBD)        return emb[wofs + k];
    if (k < EMBD+POSD)   return pos_emb[pofs + (k - EMBD)];
    if (k < INDIM)       return ner_emb[nofs + (k - EMBD - POSD)];
    return 0.f;
}

// ---------------------------------------------------------------------------
// Fused front kernel (432 blocks):
//   blocks [0,32):   denom + mask for batch b = blockIdx.x
//   blocks [32,432): preprocessor GEMM with fused embedding gather
//     C[t,j] = concat_emb(t) . Wp[j,:] + bp[j]   (32x64 tile, double-buffered)
// ---------------------------------------------------------------------------
struct PreSmem {
    float As[2][KC][BM+4];
    float Bs[2][KC][BN+4];
};

__global__ __launch_bounds__(256) void front_kernel(
        const int* __restrict__ adj,
        const int* __restrict__ words,
        const int* __restrict__ pos,
        const int* __restrict__ ner,
        const float* __restrict__ emb,
        const float* __restrict__ pos_emb,
        const float* __restrict__ ner_emb,
        const float* __restrict__ Wp,
        const float* __restrict__ bp,
        float* __restrict__ out_mask, int write_mask,
        float* __restrict__ C) {
    __shared__ __align__(16) char sbuf[NL*NL*4];   // 40 KB union
    int tid = threadIdx.x;

    if (blockIdx.x < NB) {
        // ---------------- denom + mask ----------------
        int* A = (int*)sbuf;
        int b = blockIdx.x;
        const int* src = adj + b*NL*NL;
        for (int i = tid; i < NL*NL; i += 256) A[i] = src[i];
        __syncthreads();
        if (tid < NL) {
            int rc = 0, cc = 0;
            #pragma unroll 4
            for (int m = 0; m < NL; m++) {
                rc += (A[tid*NL + m] != 0);
                cc += (A[m*NL + tid] != 0);
            }
            g_invden[b*NL + tid] = 1.0f / (float)(rc + 1);
            if (write_mask)
                out_mask[b*NL + tid] = (rc + cc == 0) ? 1.0f : 0.0f;
        }
        return;
    }

    // ---------------- gather + GEMM (K = INDIM) ----------------
    PreSmem* S = (PreSmem*)sbuf;
    const int K = INDIM;
    const int NC = (K + KC - 1) / KC;       // 23
    int idx = blockIdx.x - NB;
    int t0 = (idx >> 2) * BM;
    int j0 = (idx & 3) * BN;

    int tx = tid & 15, ty = tid >> 4;
    int lkk = tid & 15;
    int lrow = tid >> 4;                    // 0..15

    // per-thread token gather bases (two tokens)
    int ta = t0 + lrow, tb = t0 + lrow + 16;
    int wa = words[ta]*EMBD, wb = words[tb]*EMBD;
    int pa = pos[ta]*POSD,  pb = pos[tb]*POSD;
    int na = ner[ta]*NERD,  nb = ner[tb]*NERD;

    float rA[2], rB[4];

    // preload chunk 0 (k = lkk < 16, always emb region)
    rA[0] = gatherA(lkk, wa, pa, na, emb, pos_emb, ner_emb);
    rA[1] = gatherA(lkk, wb, pb, nb, emb, pos_emb, ner_emb);
    #pragma unroll
    for (int it = 0; it < 4; it++) {
        int j = lrow + it*16;
        rB[it] = ((j0 + j) < ND) ? Wp[(j0 + j)*K + lkk] : 0.f;
    }
    S->As[0][lkk][lrow]      = rA[0];
    S->As[0][lkk][lrow + 16] = rA[1];
    #pragma unroll
    for (int it = 0; it < 4; it++) S->Bs[0][lkk][lrow + it*16] = rB[it];
    __syncthreads();

    float acc[2][4];
    #pragma unroll
    for (int i = 0; i < 2; i++)
        #pragma unroll
        for (int j = 0; j < 4; j++) acc[i][j] = 0.f;

    for (int c = 0; c < NC; c++) {
        int cur = c & 1;
        if (c + 1 < NC) {
            int k = (c + 1) * KC + lkk;
            rA[0] = gatherA(k, wa, pa, na, emb, pos_emb, ner_emb);
            rA[1] = gatherA(k, wb, pb, nb, emb, pos_emb, ner_emb);
            #pragma unroll
            for (int it = 0; it < 4; it++) {
                int j = lrow + it*16;
                rB[it] = (k < K && (j0 + j) < ND) ? Wp[(j0 + j)*K + k] : 0.f;
            }
        }
        #pragma unroll
        for (int kk = 0; kk < KC; kk++) {
            float2 a = *(const float2*)&S->As[cur][kk][2*tx];
            float4 b = *(const float4*)&S->Bs[cur][kk][4*ty];
            acc[0][0] += a.x*b.x; acc[0][1] += a.x*b.y; acc[0][2] += a.x*b.z; acc[0][3] += a.x*b.w;
            acc[1][0] += a.y*b.x; acc[1][1] += a.y*b.y; acc[1][2] += a.y*b.z; acc[1][3] += a.y*b.w;
        }
        if (c + 1 < NC) {
            int nxt = cur ^ 1;
            S->As[nxt][lkk][lrow]      = rA[0];
            S->As[nxt][lkk][lrow + 16] = rA[1];
            #pragma unroll
            for (int it = 0; it < 4; it++) S->Bs[nxt][lkk][lrow + it*16] = rB[it];
        }
        __syncthreads();
    }

    int tbase = t0 + 2*tx;
    int jbase = j0 + 4*ty;
    #pragma unroll
    for (int i = 0; i < 2; i++) {
        int tok = tbase + i;
        if (jbase + 3 < ND) {
            float4 v;
            v.x = acc[i][0] + bp[jbase];
            v.y = acc[i][1] + bp[jbase+1];
            v.z = acc[i][2] + bp[jbase+2];
            v.w = acc[i][3] + bp[jbase+3];
            *(float4*)&C[tok*ND + jbase] = v;
        } else {
            #pragma unroll
            for (int j = 0; j < 4; j++)
                if (jbase + j < ND)
                    C[tok*ND + jbase + j] = acc[i][j] + bp[jbase + j];
        }
    }
}

// ---------------------------------------------------------------------------
// Layer GEMM: C[t,j] = relu((Z[t,:].W[j,:] + 2*b[j]) * invden[t])
// Block 32x64, 256 thr, 2x4 per thread, double-buffered (R6 measured winner).
// ---------------------------------------------------------------------------
__global__ __launch_bounds__(256) void gemm_relu_kernel(const float* __restrict__ A,
                                                        const float* __restrict__ B,
                                                        const float* __restrict__ bias,
                                                        float* __restrict__ C) {
    const int K = ND;
    const int NC = (K + KC - 1) / KC;       // 13
    __shared__ __align__(16) float As[2][KC][BM+4];
    __shared__ __align__(16) float Bs[2][KC][BN+4];
    int tid = threadIdx.x;
    int tx = tid & 15, ty = tid >> 4;
    int t0 = blockIdx.x * BM;
    int j0 = blockIdx.y * BN;

    int lkk = tid & 15;
    int lrow = tid >> 4;

    float rA[2], rB[4];

    #pragma unroll
    for (int it = 0; it < 2; it++)
        rA[it] = A[(t0 + lrow + it*16)*K + lkk];
    #pragma unroll
    for (int it = 0; it < 4; it++) {
        int j = lrow + it*16;
        rB[it] = ((j0 + j) < ND) ? B[(j0 + j)*K + lkk] : 0.f;
    }
    #pragma unroll
    for (int it = 0; it < 2; it++) As[0][lkk][lrow + it*16] = rA[it];
    #pragma unroll
    for (int it = 0; it < 4; it++) Bs[0][lkk][lrow + it*16] = rB[it];
    __syncthreads();

    float acc[2][4];
    #pragma unroll
    for (int i = 0; i < 2; i++)
        #pragma unroll
        for (int j = 0; j < 4; j++) acc[i][j] = 0.f;

    for (int c = 0; c < NC; c++) {
        int cur = c & 1;
        if (c + 1 < NC) {
            int k = (c + 1) * KC + lkk;
            #pragma unroll
            for (int it = 0; it < 2; it++)
                rA[it] = (k < K) ? A[(t0 + lrow + it*16)*K + k] : 0.f;
            #pragma unroll
            for (int it = 0; it < 4; it++) {
                int j = lrow + it*16;
                rB[it] = (k < K && (j0 + j) < ND) ? B[(j0 + j)*K + k] : 0.f;
            }
        }
        #pragma unroll
        for (int kk = 0; kk < KC; kk++) {
            float2 a = *(const float2*)&As[cur][kk][2*tx];
            float4 b = *(const float4*)&Bs[cur][kk][4*ty];
            acc[0][0] += a.x*b.x; acc[0][1] += a.x*b.y; acc[0][2] += a.x*b.z; acc[0][3] += a.x*b.w;
            acc[1][0] += a.y*b.x; acc[1][1] += a.y*b.y; acc[1][2] += a.y*b.z; acc[1][3] += a.y*b.w;
        }
        if (c + 1 < NC) {
            int nxt = cur ^ 1;
            #pragma unroll
            for (int it = 0; it < 2; it++) As[nxt][lkk][lrow + it*16] = rA[it];
            #pragma unroll
            for (int it = 0; it < 4; it++) Bs[nxt][lkk][lrow + it*16] = rB[it];
        }
        __syncthreads();
    }

    int tbase = t0 + 2*tx;
    int jbase = j0 + 4*ty;
    #pragma unroll
    for (int i = 0; i < 2; i++) {
        int tok = tbase + i;
        float inv = g_invden[tok];
        float4 v;
        v.x = fmaxf((acc[i][0] + 2.f*bias[jbase])   * inv, 0.f);
        v.y = fmaxf((acc[i][1] + 2.f*bias[jbase+1]) * inv, 0.f);
        v.z = fmaxf((acc[i][2] + 2.f*bias[jbase+2]) * inv, 0.f);
        v.w = fmaxf((acc[i][3] + 2.f*bias[jbase+3]) * inv, 0.f);
        if (jbase + 3 < ND)
            *(float4*)&C[tok*ND + jbase] = v;
        else {
            if (jbase   < ND) C[tok*ND + jbase]   = v.x;
            if (jbase+1 < ND) C[tok*ND + jbase+1] = v.y;
            if (jbase+2 < ND) C[tok*ND + jbase+2] = v.z;
            if (jbase+3 < ND) C[tok*ND + jbase+3] = v.w;
        }
    }
}

// ---------------------------------------------------------------------------
// Aggregation (unchanged from R9 best): Z = x + sum_m E[adj[l,m]] * x[m]
// ---------------------------------------------------------------------------
__global__ __launch_bounds__(256) void agg_kernel(const int* __restrict__ adj,
                                                  const float* __restrict__ dep,
                                                  const float* __restrict__ x,
                                                  float* __restrict__ z) {
    __shared__ __align__(16) float Es[NREL*ND];        // 32 KB
    __shared__ __align__(16) int adjs[NL*4];           // 1.6 KB
    __shared__ __align__(16) float part[AGG_ROWS][ND]; // 3.2 KB
    int tid = threadIdx.x;
    int b = blockIdx.y;
    int l0 = blockIdx.x * AGG_ROWS;

    int dp = tid & 127;
    int mh = tid >> 7;
    bool active = dp < ND/2;

    ull acc[AGG_ROWS];
    if (active && mh == 0) {
        #pragma unroll
        for (int i = 0; i < AGG_ROWS; i++)
            acc[i] = *(const ull*)&x[(b*NL + l0 + i)*ND + 2*dp];
    } else {
        #pragma unroll
        for (int i = 0; i < AGG_ROWS; i++) acc[i] = 0ull;
    }

    {
        const float4* d4 = (const float4*)dep;
        float4* e4 = (float4*)Es;
        for (int i = tid; i < NREL*ND/4; i += 256) e4[i] = d4[i];
        for (int i = tid; i < AGG_ROWS*NL; i += 256) {
            int j = i & 3, m = i >> 2;
            adjs[i] = adj[(b*NL + l0 + j)*NL + m] * (ND*4);
        }
    }
    __syncthreads();

    if (active) {
        const char* ep = (const char*)Es + 8*dp;
        const float* xb = x + b*NL*ND + 2*dp + mh*MH*ND;
        const int*  ap = adjs + mh*MH*4;

        ull xv0[5], xv1[5];
        #pragma unroll
        for (int s = 0; s < 5; s++) {
            xv0[s] = *(const ull*)(xb + s*ND);
            xv1[s] = *(const ull*)(xb + (5 + s)*ND);
        }

        #pragma unroll 1
        for (int ch = 0; ch < 10; ch += 2) {
            {
                ull cv[5];
                #pragma unroll
                for (int s = 0; s < 5; s++) cv[s] = xv0[s];
                if (ch + 2 < 10) {
                    const float* px = xb + (ch + 2)*5*ND;
                    #pragma unroll
                    for (int s = 0; s < 5; s++)
                        xv0[s] = *(const ull*)(px + s*ND);
                }
                const int* apc = ap + ch*5*4;
                #pragma unroll
                for (int s = 0; s < 5; s++) {
                    const int4 r03 = *(const int4*)&apc[s*4];
                    fma2(acc[0], *(const ull*)(ep + r03.x), cv[s]);
                    fma2(acc[1], *(const ull*)(ep + r03.y), cv[s]);
                    fma2(acc[2], *(const ull*)(ep + r03.z), cv[s]);
                    fma2(acc[3], *(const ull*)(ep + r03.w), cv[s]);
                }
            }
            {
                ull cv[5];
                #pragma unroll
                for (int s = 0; s < 5; s++) cv[s] = xv1[s];
                if (ch + 3 < 10) {
                    const float* px = xb + (ch + 3)*5*ND;
                    #pragma unroll
                    for (int s = 0; s < 5; s++)
                        xv1[s] = *(const ull*)(px + s*ND);
                }
                const int* apc = ap + (ch + 1)*5*4;
                #pragma unroll
                for (int s = 0; s < 5; s++) {
                    const int4 r03 = *(const int4*)&apc[s*4];
                    fma2(acc[0], *(const ull*)(ep + r03.x), cv[s]);
                    fma2(acc[1], *(const ull*)(ep + r03.y), cv[s]);
                    fma2(acc[2], *(const ull*)(ep + r03.z), cv[s]);
                    fma2(acc[3], *(const ull*)(ep + r03.w), cv[s]);
                }
            }
        }

        if (mh == 1) {
            #pragma unroll
            for (int i = 0; i < AGG_ROWS; i++)
                *(ull*)&part[i][2*dp] = acc[i];
        }
    }
    __syncthreads();
    if (active && mh == 0) {
        #pragma unroll
        for (int i = 0; i < AGG_ROWS; i++) {
            ull p = *(const ull*)&part[i][2*dp];
            *(ull*)&z[(b*NL + l0 + i)*ND + 2*dp] = add2(acc[i], p);
        }
    }
}

// ---------------------------------------------------------------------------
extern "C" void kernel_launch(void* const* d_in, const int* in_sizes, int n_in,
                              void* d_out, int out_size) {
    const int*   adj     = (const int*)  d_in[0];
    const int*   words   = (const int*)  d_in[1];
    const int*   pos     = (const int*)  d_in[2];
    const int*   ner     = (const int*)  d_in[3];
    const float* emb     = (const float*)d_in[4];
    const float* pos_emb = (const float*)d_in[5];
    const float* ner_emb = (const float*)d_in[6];
    const float* dep     = (const float*)d_in[7];
    const float* Wp      = (const float*)d_in[8];
    const float* bp      = (const float*)d_in[9];
    const float* W0      = (const float*)d_in[10];
    const float* b0      = (const float*)d_in[11];
    const float* W1      = (const float*)d_in[12];
    const float* b1      = (const float*)d_in[13];
    float* out = (float*)d_out;

    float *xb, *z;
    cudaGetSymbolAddress((void**)&xb, g_xb);
    cudaGetSymbolAddress((void**)&z,  g_z);

    int write_mask = (out_size >= NT*ND + NT) ? 1 : 0;

    dim3 ggrid(NT/BM, (ND + BN - 1)/BN);        // (100, 4) = 400 blocks
    dim3 agrid(NL/AGG_ROWS, NB);                // (25, 32) = 800 blocks

    front_kernel<<<NB + 400, 256>>>(adj, words, pos, ner, emb, pos_emb, ner_emb,
                                    Wp, bp, out + NT*ND, write_mask, xb);
    agg_kernel<<<agrid, 256>>>(adj, dep, xb, z);
    gemm_relu_kernel<<<ggrid, 256>>>(z, W0, b0, xb);
    agg_kernel<<<agrid, 256>>>(adj, dep, xb, z);
    gemm_relu_kernel<<<ggrid, 256>>>(z, W1, b1, out);
}

// round 11
// speedup vs baseline: 1.2737x; 1.0186x over previous
#include <cuda_runtime.h>

#define NB 32
#define NL 100
#define NT (NB*NL)      // 3200 tokens
#define ND 200
#define INDIM 360
#define EMBD 300
#define POSD 30
#define NERD 30
#define NREL 40

#define BM 32           // tokens per block tile (GEMM)
#define BN 64           // outputs per block tile (GEMM)
#define KC 16           // k chunk
#define AGG_ROWS 4      // l rows per agg block
#define NQ (ND/4)       // 50 d-quads

typedef unsigned long long ull;

__device__ float g_xb[NT*ND];
__device__ float g_z[NT*ND];
__device__ float g_invden[NT];

__device__ __forceinline__ void fma2(ull& acc, ull a, ull b) {
    asm("fma.rn.f32x2 %0, %1, %2, %0;" : "+l"(acc) : "l"(a), "l"(b));
}
__device__ __forceinline__ ull add2(ull a, ull b) {
    ull r;
    asm("add.rn.f32x2 %0, %1, %2;" : "=l"(r) : "l"(a), "l"(b));
    return r;
}

// gather one element of the concatenated embedding row
__device__ __forceinline__ float gatherA(int k, int wofs, int pofs, int nofs,
                                         const float* __restrict__ emb,
                                         const float* __restrict__ pos_emb,
                                         const float* __restrict__ ner_emb) {
    if (k < EMBD)        return emb[wofs + k];
    if (k < EMBD+POSD)   return pos_emb[pofs + (k - EMBD)];
    if (k < INDIM)       return ner_emb[nofs + (k - EMBD - POSD)];
    return 0.f;
}

// ---------------------------------------------------------------------------
// Fused front kernel (432 blocks):
//   blocks [0,32):   denom + mask for batch b = blockIdx.x
//   blocks [32,432): preprocessor GEMM with fused embedding gather
// ---------------------------------------------------------------------------
struct PreSmem {
    float As[2][KC][BM+4];
    float Bs[2][KC][BN+4];
};

__global__ __launch_bounds__(256) void front_kernel(
        const int* __restrict__ adj,
        const int* __restrict__ words,
        const int* __restrict__ pos,
        const int* __restrict__ ner,
        const float* __restrict__ emb,
        const float* __restrict__ pos_emb,
        const float* __restrict__ ner_emb,
        const float* __restrict__ Wp,
        const float* __restrict__ bp,
        float* __restrict__ out_mask, int write_mask,
        float* __restrict__ C) {
    __shared__ __align__(16) char sbuf[NL*NL*4];   // 40 KB union
    int tid = threadIdx.x;

    if (blockIdx.x < NB) {
        int* A = (int*)sbuf;
        int b = blockIdx.x;
        const int* src = adj + b*NL*NL;
        for (int i = tid; i < NL*NL; i += 256) A[i] = src[i];
        __syncthreads();
        if (tid < NL) {
            int rc = 0, cc = 0;
            #pragma unroll 4
            for (int m = 0; m < NL; m++) {
                rc += (A[tid*NL + m] != 0);
                cc += (A[m*NL + tid] != 0);
            }
            g_invden[b*NL + tid] = 1.0f / (float)(rc + 1);
            if (write_mask)
                out_mask[b*NL + tid] = (rc + cc == 0) ? 1.0f : 0.0f;
        }
        return;
    }

    PreSmem* S = (PreSmem*)sbuf;
    const int K = INDIM;
    const int NC = (K + KC - 1) / KC;       // 23
    int idx = blockIdx.x - NB;
    int t0 = (idx >> 2) * BM;
    int j0 = (idx & 3) * BN;

    int tx = tid & 15, ty = tid >> 4;
    int lkk = tid & 15;
    int lrow = tid >> 4;

    int ta = t0 + lrow, tb = t0 + lrow + 16;
    int wa = words[ta]*EMBD, wb = words[tb]*EMBD;
    int pa = pos[ta]*POSD,  pb = pos[tb]*POSD;
    int na = ner[ta]*NERD,  nb = ner[tb]*NERD;

    float rA[2], rB[4];

    rA[0] = gatherA(lkk, wa, pa, na, emb, pos_emb, ner_emb);
    rA[1] = gatherA(lkk, wb, pb, nb, emb, pos_emb, ner_emb);
    #pragma unroll
    for (int it = 0; it < 4; it++) {
        int j = lrow + it*16;
        rB[it] = ((j0 + j) < ND) ? Wp[(j0 + j)*K + lkk] : 0.f;
    }
    S->As[0][lkk][lrow]      = rA[0];
    S->As[0][lkk][lrow + 16] = rA[1];
    #pragma unroll
    for (int it = 0; it < 4; it++) S->Bs[0][lkk][lrow + it*16] = rB[it];
    __syncthreads();

    float acc[2][4];
    #pragma unroll
    for (int i = 0; i < 2; i++)
        #pragma unroll
        for (int j = 0; j < 4; j++) acc[i][j] = 0.f;

    for (int c = 0; c < NC; c++) {
        int cur = c & 1;
        if (c + 1 < NC) {
            int k = (c + 1) * KC + lkk;
            rA[0] = gatherA(k, wa, pa, na, emb, pos_emb, ner_emb);
            rA[1] = gatherA(k, wb, pb, nb, emb, pos_emb, ner_emb);
            #pragma unroll
            for (int it = 0; it < 4; it++) {
                int j = lrow + it*16;
                rB[it] = (k < K && (j0 + j) < ND) ? Wp[(j0 + j)*K + k] : 0.f;
            }
        }
        #pragma unroll
        for (int kk = 0; kk < KC; kk++) {
            float2 a = *(const float2*)&S->As[cur][kk][2*tx];
            float4 b = *(const float4*)&S->Bs[cur][kk][4*ty];
            acc[0][0] += a.x*b.x; acc[0][1] += a.x*b.y; acc[0][2] += a.x*b.z; acc[0][3] += a.x*b.w;
            acc[1][0] += a.y*b.x; acc[1][1] += a.y*b.y; acc[1][2] += a.y*b.z; acc[1][3] += a.y*b.w;
        }
        if (c + 1 < NC) {
            int nxt = cur ^ 1;
            S->As[nxt][lkk][lrow]      = rA[0];
            S->As[nxt][lkk][lrow + 16] = rA[1];
            #pragma unroll
            for (int it = 0; it < 4; it++) S->Bs[nxt][lkk][lrow + it*16] = rB[it];
        }
        __syncthreads();
    }

    int tbase = t0 + 2*tx;
    int jbase = j0 + 4*ty;
    #pragma unroll
    for (int i = 0; i < 2; i++) {
        int tok = tbase + i;
        if (jbase + 3 < ND) {
            float4 v;
            v.x = acc[i][0] + bp[jbase];
            v.y = acc[i][1] + bp[jbase+1];
            v.z = acc[i][2] + bp[jbase+2];
            v.w = acc[i][3] + bp[jbase+3];
            *(float4*)&C[tok*ND + jbase] = v;
        } else {
            #pragma unroll
            for (int j = 0; j < 4; j++)
                if (jbase + j < ND)
                    C[tok*ND + jbase + j] = acc[i][j] + bp[jbase + j];
        }
    }
}

// ---------------------------------------------------------------------------
// Layer GEMM: C[t,j] = relu((Z[t,:].W[j,:] + 2*b[j]) * invden[t])
// ---------------------------------------------------------------------------
__global__ __launch_bounds__(256) void gemm_relu_kernel(const float* __restrict__ A,
                                                        const float* __restrict__ B,
                                                        const float* __restrict__ bias,
                                                        float* __restrict__ C) {
    const int K = ND;
    const int NC = (K + KC - 1) / KC;       // 13
    __shared__ __align__(16) float As[2][KC][BM+4];
    __shared__ __align__(16) float Bs[2][KC][BN+4];
    int tid = threadIdx.x;
    int tx = tid & 15, ty = tid >> 4;
    int t0 = blockIdx.x * BM;
    int j0 = blockIdx.y * BN;

    int lkk = tid & 15;
    int lrow = tid >> 4;

    float rA[2], rB[4];

    #pragma unroll
    for (int it = 0; it < 2; it++)
        rA[it] = A[(t0 + lrow + it*16)*K + lkk];
    #pragma unroll
    for (int it = 0; it < 4; it++) {
        int j = lrow + it*16;
        rB[it] = ((j0 + j) < ND) ? B[(j0 + j)*K + lkk] : 0.f;
    }
    #pragma unroll
    for (int it = 0; it < 2; it++) As[0][lkk][lrow + it*16] = rA[it];
    #pragma unroll
    for (int it = 0; it < 4; it++) Bs[0][lkk][lrow + it*16] = rB[it];
    __syncthreads();

    float acc[2][4];
    #pragma unroll
    for (int i = 0; i < 2; i++)
        #pragma unroll
        for (int j = 0; j < 4; j++) acc[i][j] = 0.f;

    for (int c = 0; c < NC; c++) {
        int cur = c & 1;
        if (c + 1 < NC) {
            int k = (c + 1) * KC + lkk;
            #pragma unroll
            for (int it = 0; it < 2; it++)
                rA[it] = (k < K) ? A[(t0 + lrow + it*16)*K + k] : 0.f;
            #pragma unroll
            for (int it = 0; it < 4; it++) {
                int j = lrow + it*16;
                rB[it] = (k < K && (j0 + j) < ND) ? B[(j0 + j)*K + k] : 0.f;
            }
        }
        #pragma unroll
        for (int kk = 0; kk < KC; kk++) {
            float2 a = *(const float2*)&As[cur][kk][2*tx];
            float4 b = *(const float4*)&Bs[cur][kk][4*ty];
            acc[0][0] += a.x*b.x; acc[0][1] += a.x*b.y; acc[0][2] += a.x*b.z; acc[0][3] += a.x*b.w;
            acc[1][0] += a.y*b.x; acc[1][1] += a.y*b.y; acc[1][2] += a.y*b.z; acc[1][3] += a.y*b.w;
        }
        if (c + 1 < NC) {
            int nxt = cur ^ 1;
            #pragma unroll
            for (int it = 0; it < 2; it++) As[nxt][lkk][lrow + it*16] = rA[it];
            #pragma unroll
            for (int it = 0; it < 4; it++) Bs[nxt][lkk][lrow + it*16] = rB[it];
        }
        __syncthreads();
    }

    int tbase = t0 + 2*tx;
    int jbase = j0 + 4*ty;
    #pragma unroll
    for (int i = 0; i < 2; i++) {
        int tok = tbase + i;
        float inv = g_invden[tok];
        float4 v;
        v.x = fmaxf((acc[i][0] + 2.f*bias[jbase])   * inv, 0.f);
        v.y = fmaxf((acc[i][1] + 2.f*bias[jbase+1]) * inv, 0.f);
        v.z = fmaxf((acc[i][2] + 2.f*bias[jbase+2]) * inv, 0.f);
        v.w = fmaxf((acc[i][3] + 2.f*bias[jbase+3]) * inv, 0.f);
        if (jbase + 3 < ND)
            *(float4*)&C[tok*ND + jbase] = v;
        else {
            if (jbase   < ND) C[tok*ND + jbase]   = v.x;
            if (jbase+1 < ND) C[tok*ND + jbase+1] = v.y;
            if (jbase+2 < ND) C[tok*ND + jbase+2] = v.z;
            if (jbase+3 < ND) C[tok*ND + jbase+3] = v.w;
        }
    }
}

// ---------------------------------------------------------------------------
// Aggregation v2 (d-quads + LDS.128):
//   Z[b,l,d] = x[b,l,d] + sum_m E[adj[b,l,m], d] * x[b,m,d]
// 256 threads = 4 groups x 64 (50 active: one d-quad each). Each group handles
// 25 m's. Es rows read via LDS.128 (uniform r per warp -> conflict-free).
// Static double-buffer prefetch, explicit 5-chunk schedule (all indices
// compile-time). Groups 1..3 write partials; group 0 combines.
// ---------------------------------------------------------------------------

// process 5 m's: copy BUF->cv, optionally refill BUF from chunk at PB, compute
#define AGG_CHUNK(BUF, MB, DOPRE, PB)                                        \
  {                                                                          \
    longlong2 cv[5];                                                         \
    _Pragma("unroll") for (int s = 0; s < 5; s++) cv[s] = BUF[s];            \
    if (DOPRE) {                                                             \
      _Pragma("unroll") for (int s = 0; s < 5; s++)                          \
        BUF[s] = *(const longlong2*)(xq + ((PB) + s)*ND);                    \
    }                                                                        \
    _Pragma("unroll") for (int s = 0; s < 5; s++) {                          \
      const int4 r = *(const int4*)&adjs[((MB) + s)*4];                      \
      ull lo = (ull)cv[s].x, hi = (ull)cv[s].y;                              \
      longlong2 e;                                                           \
      e = *(const longlong2*)(ep + r.x);                                     \
      fma2(acc0[0], (ull)e.x, lo); fma2(acc1[0], (ull)e.y, hi);              \
      e = *(const longlong2*)(ep + r.y);                                     \
      fma2(acc0[1], (ull)e.x, lo); fma2(acc1[1], (ull)e.y, hi);              \
      e = *(const longlong2*)(ep + r.z);                                     \
      fma2(acc0[2], (ull)e.x, lo); fma2(acc1[2], (ull)e.y, hi);              \
      e = *(const longlong2*)(ep + r.w);                                     \
      fma2(acc0[3], (ull)e.x, lo); fma2(acc1[3], (ull)e.y, hi);              \
    }                                                                        \
  }

__global__ __launch_bounds__(256) void agg_kernel(const int* __restrict__ adj,
                                                  const float* __restrict__ dep,
                                                  const float* __restrict__ x,
                                                  float* __restrict__ z) {
    __shared__ __align__(16) float Es[NREL*ND];           // 32 KB
    __shared__ __align__(16) int adjs[NL*4];              // 1.6 KB
    __shared__ __align__(16) float part[3][AGG_ROWS][ND]; // 9.6 KB
    int tid = threadIdx.x;
    int b = blockIdx.y;
    int l0 = blockIdx.x * AGG_ROWS;

    int g  = tid >> 6;           // m-quarter group 0..3
    int qd = tid & 63;           // d-quad index (active if < 50)
    bool active = qd < NQ;

    // init accumulators (group 0 seeds with x row quads) — overlaps staging
    ull acc0[AGG_ROWS], acc1[AGG_ROWS];
    if (active && g == 0) {
        #pragma unroll
        for (int i = 0; i < AGG_ROWS; i++) {
            longlong2 t = *(const longlong2*)&x[(b*NL + l0 + i)*ND + 4*qd];
            acc0[i] = (ull)t.x; acc1[i] = (ull)t.y;
        }
    } else {
        #pragma unroll
        for (int i = 0; i < AGG_ROWS; i++) { acc0[i] = 0ull; acc1[i] = 0ull; }
    }

    // stage Es (float4) and adjs (byte offsets into Es)
    {
        const float4* d4 = (const float4*)dep;
        float4* e4 = (float4*)Es;
        for (int i = tid; i < NREL*ND/4; i += 256) e4[i] = d4[i];
        for (int i = tid; i < AGG_ROWS*NL; i += 256) {
            int j = i & 3, m = i >> 2;
            adjs[i] = adj[(b*NL + l0 + j)*NL + m] * (ND*4);
        }
    }
    __syncthreads();

    if (active) {
        const char* ep = (const char*)Es + 16*qd;
        const float* xq = x + b*NL*ND + 4*qd + g*25*ND;  // group's m-range base
        int mb = g*25;                                   // adjs base (absolute m)

        longlong2 v0[5], v1[5];
        #pragma unroll
        for (int s = 0; s < 5; s++) {
            v0[s] = *(const longlong2*)(xq + s*ND);
            v1[s] = *(const longlong2*)(xq + (5 + s)*ND);
        }

        AGG_CHUNK(v0, mb + 0,  true, 10)
        AGG_CHUNK(v1, mb + 5,  true, 15)
        AGG_CHUNK(v0, mb + 10, true, 20)
        AGG_CHUNK(v1, mb + 15, false, 0)
        AGG_CHUNK(v0, mb + 20, false, 0)

        if (g > 0) {
            #pragma unroll
            for (int i = 0; i < AGG_ROWS; i++) {
                longlong2 t;
                t.x = (long long)acc0[i]; t.y = (long long)acc1[i];
                *(longlong2*)&part[g-1][i][4*qd] = t;
            }
        }
    }
    __syncthreads();
    if (active && g == 0) {
        #pragma unroll
        for (int i = 0; i < AGG_ROWS; i++) {
            #pragma unroll
            for (int p = 0; p < 3; p++) {
                longlong2 t = *(const longlong2*)&part[p][i][4*qd];
                acc0[i] = add2(acc0[i], (ull)t.x);
                acc1[i] = add2(acc1[i], (ull)t.y);
            }
            longlong2 o;
            o.x = (long long)acc0[i]; o.y = (long long)acc1[i];
            *(longlong2*)&z[(b*NL + l0 + i)*ND + 4*qd] = o;
        }
    }
}

// ---------------------------------------------------------------------------
extern "C" void kernel_launch(void* const* d_in, const int* in_sizes, int n_in,
                              void* d_out, int out_size) {
    const int*   adj     = (const int*)  d_in[0];
    const int*   words   = (const int*)  d_in[1];
    const int*   pos     = (const int*)  d_in[2];
    const int*   ner     = (const int*)  d_in[3];
    const float* emb     = (const float*)d_in[4];
    const float* pos_emb = (const float*)d_in[5];
    const float* ner_emb = (const float*)d_in[6];
    const float* dep     = (const float*)d_in[7];
    const float* Wp      = (const float*)d_in[8];
    const float* bp      = (const float*)d_in[9];
    const float* W0      = (const float*)d_in[10];
    const float* b0      = (const float*)d_in[11];
    const float* W1      = (const float*)d_in[12];
    const float* b1      = (const float*)d_in[13];
    float* out = (float*)d_out;

    float *xb, *z;
    cudaGetSymbolAddress((void**)&xb, g_xb);
    cudaGetSymbolAddress((void**)&z,  g_z);

    int write_mask = (out_size >= NT*ND + NT) ? 1 : 0;

    dim3 ggrid(NT/BM, (ND + BN - 1)/BN);        // (100, 4) = 400 blocks
    dim3 agrid(NL/AGG_ROWS, NB);                // (25, 32) = 800 blocks

    front_kernel<<<NB + 400, 256>>>(adj, words, pos, ner, emb, pos_emb, ner_emb,
                                    Wp, bp, out + NT*ND, write_mask, xb);
    agg_kernel<<<agrid, 256>>>(adj, dep, xb, z);
    gemm_relu_kernel<<<ggrid, 256>>>(z, W0, b0, xb);
    agg_kernel<<<agrid, 256>>>(adj, dep, xb, z);
    gemm_relu_kernel<<<ggrid, 256>>>(z, W1, b1, out);
}